// round 16
// baseline (speedup 1.0000x reference)
#include <cuda_runtime.h>
#include <cuda_fp16.h>
#include <stdint.h>
#include <math.h>

#define N_NODES 10000
#define N_EDGES 320000

// ---------------- scratch (static device allocations) ----------------
__device__ __half g_C1[N_NODES * 512];   // fp16: x@(W1top-W1bot) + b1
__device__ __half g_D1[N_NODES * 512];   // fp16: x@W1bot
__device__ float  g_H1[N_NODES * 256];
__device__ __half g_C2[N_NODES * 256];
__device__ __half g_D2[N_NODES * 256];
__device__ float  g_H2[N_NODES * 128];
__device__ int    g_hist[N_NODES + 1];
__device__ int    g_bsum[32];
__device__ int    g_cursor[N_NODES];
__device__ int    g_src_s[N_EDGES];
__device__ int    g_dst_s[N_EDGES];
__device__ __half g_WT1[256 * 512];
__device__ __half g_WT2[128 * 256];
__device__ __half g_WTD1[1024 * 128];
__device__ __half g_WTD2[512 * 256];

// ---------------- one-time stream/event creation (static init, pre-checkpoint) ----
struct GraphFork {
    cudaStream_t s;
    cudaEvent_t e0, e1;
    GraphFork() {
        cudaStreamCreateWithFlags(&s, cudaStreamNonBlocking);
        cudaEventCreateWithFlags(&e0, cudaEventDisableTiming);
        cudaEventCreateWithFlags(&e1, cudaEventDisableTiming);
    }
};
static GraphFork g_fork;

// ---------------- helpers ----------------
__device__ __forceinline__ uint32_t smem_u32(const void* p) {
    uint32_t a;
    asm("{ .reg .u64 t; cvta.to.shared.u64 t, %1; cvt.u32.u64 %0, t; }" : "=r"(a) : "l"(p));
    return a;
}
__device__ __forceinline__ void mma_f16(float* c,
    uint32_t a0, uint32_t a1, uint32_t a2, uint32_t a3,
    uint32_t b0, uint32_t b1) {
    asm volatile(
        "mma.sync.aligned.m16n8k16.row.col.f32.f16.f16.f32 "
        "{%0,%1,%2,%3}, {%4,%5,%6,%7}, {%8,%9}, {%0,%1,%2,%3};"
        : "+f"(c[0]), "+f"(c[1]), "+f"(c[2]), "+f"(c[3])
        : "r"(a0), "r"(a1), "r"(a2), "r"(a3), "r"(b0), "r"(b1));
}
// fp16-accumulator variant: C/D are 2x f16x2 regs
__device__ __forceinline__ void mma_f16h(uint32_t* c,
    uint32_t a0, uint32_t a1, uint32_t a2, uint32_t a3,
    uint32_t b0, uint32_t b1) {
    asm volatile(
        "mma.sync.aligned.m16n8k16.row.col.f16.f16.f16.f16 "
        "{%0,%1}, {%2,%3,%4,%5}, {%6,%7}, {%0,%1};"
        : "+r"(c[0]), "+r"(c[1])
        : "r"(a0), "r"(a1), "r"(a2), "r"(a3), "r"(b0), "r"(b1));
}
__device__ __forceinline__ void ldsm4(uint32_t& r0, uint32_t& r1, uint32_t& r2, uint32_t& r3,
                                      uint32_t addr) {
    asm volatile("ldmatrix.sync.aligned.m8n8.x4.shared.b16 {%0,%1,%2,%3}, [%4];"
        : "=r"(r0), "=r"(r1), "=r"(r2), "=r"(r3) : "r"(addr));
}
__device__ __forceinline__ uint32_t haddrelu2(uint32_t a, uint32_t b) {
    __half2 av = *reinterpret_cast<__half2*>(&a);
    __half2 bv = *reinterpret_cast<__half2*>(&b);
    __half2 r = __hmax2(__hadd2(av, bv), __float2half2_rn(0.f));
    return *reinterpret_cast<uint32_t*>(&r);
}
__device__ __forceinline__ void cp16(uint32_t dst, const void* src) {
    asm volatile("cp.async.ca.shared.global [%0], [%1], 16;" :: "r"(dst), "l"(src) : "memory");
}
__device__ __forceinline__ void cp_commit() {
    asm volatile("cp.async.commit_group;" ::: "memory");
}
__device__ __forceinline__ void cp_wait_all() {
    asm volatile("cp.async.wait_group 0;" ::: "memory");
}

// lane offsets for LDSM fragment addressing (144B row stride tiles)
#define A_LANE_OFF(lid) ((uint32_t)(((lid) & 15) * 144 + ((lid) >> 4) * 16))
#define B_LANE_OFF(lid) ((uint32_t)(((((lid) >> 4) & 1) * 8 + ((lid) & 7)) * 144 + (((lid) >> 3) & 1) * 16))

// ---------------- init: hist/cursor/H1/H2 (branch A head) ----------------
__global__ void k_zero() {
    int stride = gridDim.x * blockDim.x;
    int i0 = blockIdx.x * blockDim.x + threadIdx.x;
    float4 z4 = make_float4(0.f, 0.f, 0.f, 0.f);
    for (int j = i0; j < N_NODES * 64; j += stride) ((float4*)g_H1)[j] = z4;
    for (int j = i0; j < N_NODES * 32; j += stride) ((float4*)g_H2)[j] = z4;
    for (int j = i0; j <= N_NODES;     j += stride) g_hist[j] = 0;
    for (int j = i0; j < N_NODES;      j += stride) g_cursor[j] = 0;
}

// ---------------- histogram (branch A) ----------------
__global__ void k_hist(const int* __restrict__ dst) {
    int e = blockIdx.x * blockDim.x + threadIdx.x;
    if (e < N_EDGES) atomicAdd(&g_hist[dst[e] + 1], 1);
}

// ---------------- weight preps (branch B) ----------------
__global__ void k_prep(const float* __restrict__ W2a, const float* __restrict__ W2b,
                       const float* __restrict__ W1a, const float* __restrict__ W1b) {
    int i = blockIdx.x * blockDim.x + threadIdx.x;
    if (i < 131072) {
        int n = i >> 9, k = i & 511;       // WT1: [256,512] from W2a [512,256]
        g_WT1[i] = __float2half_rn(W2a[k * 256 + n]);
    } else if (i < 163840) {
        int i2 = i - 131072;               // WT2: [128,256] from W2b [256,128]
        int n = i2 >> 8, k = i2 & 255;
        g_WT2[i2] = __float2half_rn(W2b[k * 128 + n]);
    } else if (i < 229376) {
        int i2 = i - 163840;               // WTD1: dual [1024,128] from W1a [256,512]
        int n = i2 >> 7, k = i2 & 127;
        float top = W1a[k * 512 + n];
        float bot = W1a[(128 + k) * 512 + n];
        g_WTD1[n * 128 + k] = __float2half_rn(top - bot);
        g_WTD1[(512 + n) * 128 + k] = __float2half_rn(bot);
    } else if (i < 294912) {
        int i2 = i - 229376;               // WTD2: dual [512,256] from W1b [512,256]
        int n = i2 >> 8, k = i2 & 255;
        float top = W1b[k * 256 + n];
        float bot = W1b[(256 + k) * 256 + n];
        g_WTD2[n * 256 + k] = __float2half_rn(top - bot);
        g_WTD2[(256 + n) * 256 + k] = __float2half_rn(bot);
    }
}

// ---------------- counting-sort scan + scatter (branch A) ----------------
__global__ void k_scan1() {
    __shared__ int s[512];
    int b = blockIdx.x, t = threadIdx.x;
    int i = b * 512 + t;
    int v = (i < N_NODES + 1) ? g_hist[i] : 0;
    s[t] = v;
    __syncthreads();
    for (int off = 1; off < 512; off <<= 1) {
        int u = (t >= off) ? s[t - off] : 0;
        __syncthreads();
        s[t] += u;
        __syncthreads();
    }
    if (i < N_NODES + 1) g_hist[i] = s[t];
    if (t == 511) g_bsum[b] = s[511];
}
__global__ void k_scatter(const int* __restrict__ src, const int* __restrict__ dst) {
    __shared__ int lut[20];
    int t = threadIdx.x;
    if (t < 32) {
        int v = (t < 20) ? g_bsum[t] : 0;
        int inc = v;
#pragma unroll
        for (int off = 1; off < 32; off <<= 1) {
            int u = __shfl_up_sync(0xffffffffu, inc, off);
            if (t >= off) inc += u;
        }
        if (t < 20) lut[t] = inc - v;   // exclusive prefix
    }
    __syncthreads();
    int e = blockIdx.x * blockDim.x + t;
    if (e < N_EDGES) {
        int d = dst[e];
        int pos = g_hist[d] + lut[d >> 9] + atomicAdd(&g_cursor[d], 1);
        g_src_s[pos] = src[e];
        g_dst_s[pos] = d;
    }
}

// ---------------- node fp16 MMA GEMM (fp32 acc): [C | D] = fp16(X) @ WTdual^T --------
#define NODE_SMEM 36864

template <int K, int NOUT>
__global__ void __launch_bounds__(256, 2) k_node_mma(
    const float* __restrict__ X, const __half* __restrict__ WT,
    const float* __restrict__ b1, __half* __restrict__ C, __half* __restrict__ D)
{
    extern __shared__ char smem[];
    const uint32_t sb = smem_u32(smem);
    const int tid = threadIdx.x;
    const int wid = tid >> 5, lid = tid & 31;
    const int warp_m = wid & 3, warp_n = wid >> 2;
    const int gid = lid >> 2, tig = lid & 3;

    const int m0 = blockIdx.x * 128;
    const int n0 = blockIdx.y * 128;

    const int fm = tid >> 1;
    const int fk = (tid & 1) * 32;
    const int gm = m0 + fm;
    const bool valid = gm < N_NODES;
    const float* rowX = X + (size_t)(valid ? gm : 0) * K + fk;
    const __half* rowW = WT + (size_t)(n0 + fm) * K + fk;

    const uint32_t aA = sb + (uint32_t)(warp_m * 32) * 144 + A_LANE_OFF(lid);
    const uint32_t aB = sb + 18432 + (uint32_t)(warp_n * 64) * 144 + B_LANE_OFF(lid);

    float acc[2][8][4];
#pragma unroll
    for (int a = 0; a < 2; ++a)
#pragma unroll
        for (int b = 0; b < 8; ++b)
#pragma unroll
            for (int c = 0; c < 4; ++c) acc[a][b][c] = 0.f;

    constexpr int NCH = K / 64;
#pragma unroll 1
    for (int ch = 0; ch < NCH; ++ch) {
        {
            const uint4* wp = (const uint4*)(rowW + ch * 64);
            uint4 w0 = wp[0], w1 = wp[1], w2 = wp[2], w3 = wp[3];
            char* pb = smem + 18432 + fm * 144 + fk * 2;
            *(uint4*)pb        = w0;
            *(uint4*)(pb + 16) = w1;
            *(uint4*)(pb + 32) = w2;
            *(uint4*)(pb + 48) = w3;
        }
        {
            char* pa = smem + fm * 144 + fk * 2;
#pragma unroll
            for (int q = 0; q < 4; ++q) {
                float4 x0 = make_float4(0.f, 0.f, 0.f, 0.f);
                float4 x1 = make_float4(0.f, 0.f, 0.f, 0.f);
                if (valid) {
                    x0 = *(const float4*)(rowX + ch * 64 + q * 8);
                    x1 = *(const float4*)(rowX + ch * 64 + q * 8 + 4);
                }
                __half2 h0 = __floats2half2_rn(x0.x, x0.y);
                __half2 h1 = __floats2half2_rn(x0.z, x0.w);
                __half2 h2 = __floats2half2_rn(x1.x, x1.y);
                __half2 h3 = __floats2half2_rn(x1.z, x1.w);
                *(uint4*)(pa + q * 16) = make_uint4(
                    *(uint32_t*)&h0, *(uint32_t*)&h1, *(uint32_t*)&h2, *(uint32_t*)&h3);
            }
        }
        __syncthreads();
#pragma unroll
        for (int ks = 0; ks < 4; ++ks) {
            uint32_t a[2][4];
            ldsm4(a[0][0], a[0][1], a[0][2], a[0][3], aA + ks * 32);
            ldsm4(a[1][0], a[1][1], a[1][2], a[1][3], aA + 16 * 144 + ks * 32);
#pragma unroll
            for (int p = 0; p < 4; ++p) {
                uint32_t b0, b1v, b2v, b3v;
                ldsm4(b0, b1v, b2v, b3v, aB + (uint32_t)(p * 16) * 144 + ks * 32);
                mma_f16(acc[0][p * 2],     a[0][0], a[0][1], a[0][2], a[0][3], b0, b1v);
                mma_f16(acc[1][p * 2],     a[1][0], a[1][1], a[1][2], a[1][3], b0, b1v);
                mma_f16(acc[0][p * 2 + 1], a[0][0], a[0][1], a[0][2], a[0][3], b2v, b3v);
                mma_f16(acc[1][p * 2 + 1], a[1][0], a[1][1], a[1][2], a[1][3], b2v, b3v);
            }
        }
        __syncthreads();
    }

    const bool isC = (n0 < NOUT);
    __half* OUT = isC ? C : D;
    const int cb = isC ? n0 : n0 - NOUT;
#pragma unroll
    for (int mt = 0; mt < 2; ++mt)
#pragma unroll
        for (int j = 0; j < 8; ++j) {
            int r = m0 + warp_m * 32 + mt * 16 + gid;
            int c = cb + warp_n * 64 + j * 8 + tig * 2;
            float bb0 = 0.f, bb1 = 0.f;
            if (isC) { bb0 = __ldg(b1 + c); bb1 = __ldg(b1 + c + 1); }
            if (r < N_NODES) {
                __half2 h = __floats2half2_rn(acc[mt][j][0] + bb0, acc[mt][j][1] + bb1);
                *(__half2*)&OUT[(size_t)r * NOUT + c] = h;
            }
            if (r + 8 < N_NODES) {
                __half2 h = __floats2half2_rn(acc[mt][j][2] + bb0, acc[mt][j][3] + bb1);
                *(__half2*)&OUT[(size_t)(r + 8) * NOUT + c] = h;
            }
        }
}

// ---------------- layer-2 edge GEMM: 256 thr, tile 128x128, fp16 acc ----------------
#define SM_SDST 0
#define SM_SSRC 512
#define SM_A0   1024
#define SM_A1   19456
#define SM_B0   37888
#define SM_B1   56320
#define SM_STG  1024
#define EDGE_SMEM 74752

template <int KW, int NOUT>
__global__ void __launch_bounds__(256, 2) k_edge_mma(
    const __half* __restrict__ C, const __half* __restrict__ D,
    const __half* __restrict__ WT, const float* __restrict__ b2, float* __restrict__ AGG)
{
    extern __shared__ char smem[];
    const uint32_t sb = smem_u32(smem);
    const int tid = threadIdx.x;
    const int wid = tid >> 5, lid = tid & 31;
    const int warp_m = wid & 3, warp_n = wid >> 2;
    const int gid = lid >> 2, tig = lid & 3;

    int* sdst = (int*)(smem + SM_SDST);
    int* ssrc = (int*)(smem + SM_SSRC);

    const int e0 = blockIdx.x * 128;
    const int n0 = blockIdx.y * 128;
    if (tid < 128) {
        sdst[tid] = g_dst_s[e0 + tid];
        ssrc[tid] = g_src_s[e0 + tid];
    }
    __syncthreads();

    const int fm = tid >> 1;
    const int fk = (tid & 1) * 32;
    const __half* rowC = C + (size_t)sdst[fm] * KW + fk;
    const __half* rowD = D + (size_t)ssrc[fm] * KW + fk;
    const __half* rowW = WT + (size_t)(n0 + fm) * KW + fk;
    const uint32_t bdst0 = sb + SM_B0 + fm * 144 + fk * 2;
    const uint32_t bdst1 = sb + SM_B1 + fm * 144 + fk * 2;

    const uint32_t aOffA = (uint32_t)(warp_m * 32) * 144 + A_LANE_OFF(lid);
    const uint32_t aOffB = (uint32_t)(warp_n * 64) * 144 + B_LANE_OFF(lid);

    uint32_t hacc[2][8][2];
#pragma unroll
    for (int a = 0; a < 2; ++a)
#pragma unroll
        for (int b = 0; b < 8; ++b) { hacc[a][b][0] = 0u; hacc[a][b][1] = 0u; }

    constexpr int NCH = KW / 64;
    uint4 pc[4], pd[4];
    {
        const uint4* cp = (const uint4*)rowC;
        const uint4* dp = (const uint4*)rowD;
#pragma unroll
        for (int q = 0; q < 4; ++q) { pc[q] = cp[q]; pd[q] = dp[q]; }
        cp16(bdst0,      rowW);
        cp16(bdst0 + 16, rowW + 8);
        cp16(bdst0 + 32, rowW + 16);
        cp16(bdst0 + 48, rowW + 24);
        cp_commit();
    }

#pragma unroll 1
    for (int ch = 0; ch < NCH; ++ch) {
        uint4 ao[4];
#pragma unroll
        for (int q = 0; q < 4; ++q) {
            ao[q].x = haddrelu2(pc[q].x, pd[q].x);
            ao[q].y = haddrelu2(pc[q].y, pd[q].y);
            ao[q].z = haddrelu2(pc[q].z, pd[q].z);
            ao[q].w = haddrelu2(pc[q].w, pd[q].w);
        }
        if (ch + 1 < NCH) {   // early gather issue
            const uint4* cp = (const uint4*)(rowC + (ch + 1) * 64);
            const uint4* dp = (const uint4*)(rowD + (ch + 1) * 64);
#pragma unroll
            for (int q = 0; q < 4; ++q) { pc[q] = cp[q]; pd[q] = dp[q]; }
        }
        {
            char* pa = smem + ((ch & 1) ? SM_A1 : SM_A0) + fm * 144 + fk * 2;
            *(uint4*)pa        = ao[0];
            *(uint4*)(pa + 16) = ao[1];
            *(uint4*)(pa + 32) = ao[2];
            *(uint4*)(pa + 48) = ao[3];
        }
        cp_wait_all();
        __syncthreads();
        if (ch + 1 < NCH) {
            const __half* ws = rowW + (ch + 1) * 64;
            uint32_t bd = ((ch + 1) & 1) ? bdst1 : bdst0;
            cp16(bd,      ws);
            cp16(bd + 16, ws + 8);
            cp16(bd + 32, ws + 16);
            cp16(bd + 48, ws + 24);
            cp_commit();
        }
        const uint32_t abase = sb + ((ch & 1) ? SM_A1 : SM_A0) + aOffA;
        const uint32_t bbase = sb + ((ch & 1) ? SM_B1 : SM_B0) + aOffB;
#pragma unroll
        for (int ks = 0; ks < 4; ++ks) {
            uint32_t a[2][4];
            ldsm4(a[0][0], a[0][1], a[0][2], a[0][3], abase + ks * 32);
            ldsm4(a[1][0], a[1][1], a[1][2], a[1][3], abase + 16 * 144 + ks * 32);
#pragma unroll
            for (int p = 0; p < 4; ++p) {
                uint32_t b0, b1v, b2v, b3v;
                ldsm4(b0, b1v, b2v, b3v, bbase + (uint32_t)(p * 16) * 144 + ks * 32);
                mma_f16h(hacc[0][p * 2],     a[0][0], a[0][1], a[0][2], a[0][3], b0, b1v);
                mma_f16h(hacc[1][p * 2],     a[1][0], a[1][1], a[1][2], a[1][3], b0, b1v);
                mma_f16h(hacc[0][p * 2 + 1], a[0][0], a[0][1], a[0][2], a[0][3], b2v, b3v);
                mma_f16h(hacc[1][p * 2 + 1], a[1][0], a[1][1], a[1][2], a[1][3], b2v, b3v);
            }
        }
    }
    __syncthreads();   // protect stage region (overlaps A/B buffers)

    // ---- epilogue: single pass, all 128 cols staged (stride 130 floats)
    float* stage = (float*)(smem + SM_STG);
#pragma unroll
    for (int mt = 0; mt < 2; ++mt)
#pragma unroll
        for (int j = 0; j < 8; ++j) {
            int r0 = warp_m * 32 + mt * 16 + gid;
            int cw = warp_n * 64 + j * 8 + tig * 2;
            float* st = stage + r0 * 130 + cw;
            float2 lo = __half22float2(*(__half2*)&hacc[mt][j][0]);
            float2 hi = __half22float2(*(__half2*)&hacc[mt][j][1]);
            st[0] = lo.x;
            st[1] = lo.y;
            st[130 * 8] = hi.x;
            st[130 * 8 + 1] = hi.y;
        }
    __syncthreads();
    {
        int colw = tid & 127;
        int grp = tid >> 7;
        int gcol = n0 + colw;
        float bias = b2[gcol];
        int prev = -1;
        float mx = 0.f;
#pragma unroll 4
        for (int r = grp * 64; r < grp * 64 + 64; ++r) {
            int d = sdst[r];
            float v = fmaxf(stage[r * 130 + colw] + bias, 0.f);
            if (d == prev) {
                mx = fmaxf(mx, v);
            } else {
                if (prev >= 0)
                    atomicMax((int*)&AGG[(size_t)prev * NOUT + gcol], __float_as_int(mx));
                prev = d;
                mx = v;
            }
        }
        atomicMax((int*)&AGG[(size_t)prev * NOUT + gcol], __float_as_int(mx));
    }
}

// ---------------- layer-1 edge GEMM: 512 thr, tile 128x256, fp16 acc ----------------
#define WSM_A0 1024
#define WSM_A1 19456
#define WSM_B0 37888
#define WSM_B1 74752
#define WEDGE_SMEM 111616

template <int KW, int NOUT>
__global__ void __launch_bounds__(512, 1) k_edge_wide(
    const __half* __restrict__ C, const __half* __restrict__ D,
    const __half* __restrict__ WT, const float* __restrict__ b2, float* __restrict__ AGG)
{
    extern __shared__ char smem[];
    const uint32_t sb = smem_u32(smem);
    const int tid = threadIdx.x;
    const int wid = tid >> 5, lid = tid & 31;
    const int warp_m = wid & 3, warp_n = wid >> 2;   // 4 x 4
    const int gid = lid >> 2, tig = lid & 3;

    int* sdst = (int*)(smem + SM_SDST);
    int* ssrc = (int*)(smem + SM_SSRC);

    const int e0 = blockIdx.x * 128;
    if (tid < 128) {
        sdst[tid] = g_dst_s[e0 + tid];
        ssrc[tid] = g_src_s[e0 + tid];
    }
    __syncthreads();

    const int fm = tid >> 2;
    const int fq = (tid & 3) * 16;
    const int wm = tid >> 1;
    const int wq = (tid & 1) * 32;
    const __half* rowC = C + (size_t)sdst[fm] * KW + fq;
    const __half* rowD = D + (size_t)ssrc[fm] * KW + fq;
    const __half* rowW = WT + (size_t)wm * KW + wq;
    const uint32_t bdst0 = sb + WSM_B0 + wm * 144 + wq * 2;
    const uint32_t bdst1 = sb + WSM_B1 + wm * 144 + wq * 2;

    const uint32_t aOffA = (uint32_t)(warp_m * 32) * 144 + A_LANE_OFF(lid);
    const uint32_t aOffB = (uint32_t)(warp_n * 64) * 144 + B_LANE_OFF(lid);

    uint32_t hacc[2][8][2];
#pragma unroll
    for (int a = 0; a < 2; ++a)
#pragma unroll
        for (int b = 0; b < 8; ++b) { hacc[a][b][0] = 0u; hacc[a][b][1] = 0u; }

    constexpr int NCH = KW / 64;
    uint4 pc[2], pd[2];
    {
        const uint4* cp = (const uint4*)rowC;
        const uint4* dp = (const uint4*)rowD;
        pc[0] = cp[0]; pc[1] = cp[1];
        pd[0] = dp[0]; pd[1] = dp[1];
        cp16(bdst0,      rowW);
        cp16(bdst0 + 16, rowW + 8);
        cp16(bdst0 + 32, rowW + 16);
        cp16(bdst0 + 48, rowW + 24);
        cp_commit();
    }

#pragma unroll 1
    for (int ch = 0; ch < NCH; ++ch) {
        uint4 ao[2];
#pragma unroll
        for (int q = 0; q < 2; ++q) {
            ao[q].x = haddrelu2(pc[q].x, pd[q].x);
            ao[q].y = haddrelu2(pc[q].y, pd[q].y);
            ao[q].z = haddrelu2(pc[q].z, pd[q].z);
            ao[q].w = haddrelu2(pc[q].w, pd[q].w);
        }
        if (ch + 1 < NCH) {   // early gather issue
            const uint4* cp = (const uint4*)(rowC + (ch + 1) * 64);
            const uint4* dp = (const uint4*)(rowD + (ch + 1) * 64);
            pc[0] = cp[0]; pc[1] = cp[1];
            pd[0] = dp[0]; pd[1] = dp[1];
        }
        {
            char* pa = smem + ((ch & 1) ? WSM_A1 : WSM_A0) + fm * 144 + fq * 2;
            *(uint4*)pa        = ao[0];
            *(uint4*)(pa + 16) = ao[1];
        }
        cp_wait_all();
        __syncthreads();
        if (ch + 1 < NCH) {
            const __half* ws = rowW + (ch + 1) * 64;
            uint32_t bd = ((ch + 1) & 1) ? bdst1 : bdst0;
            cp16(bd,      ws);
            cp16(bd + 16, ws + 8);
            cp16(bd + 32, ws + 16);
            cp16(bd + 48, ws + 24);
            cp_commit();
        }
        const uint32_t abase = sb + ((ch & 1) ? WSM_A1 : WSM_A0) + aOffA;
        const uint32_t bbase = sb + ((ch & 1) ? WSM_B1 : WSM_B0) + aOffB;
#pragma unroll
        for (int ks = 0; ks < 4; ++ks) {
            uint32_t a[2][4];
            ldsm4(a[0][0], a[0][1], a[0][2], a[0][3], abase + ks * 32);
            ldsm4(a[1][0], a[1][1], a[1][2], a[1][3], abase + 16 * 144 + ks * 32);
#pragma unroll
            for (int p = 0; p < 4; ++p) {
                uint32_t b0, b1v, b2v, b3v;
                ldsm4(b0, b1v, b2v, b3v, bbase + (uint32_t)(p * 16) * 144 + ks * 32);
                mma_f16h(hacc[0][p * 2],     a[0][0], a[0][1], a[0][2], a[0][3], b0, b1v);
                mma_f16h(hacc[1][p * 2],     a[1][0], a[1][1], a[1][2], a[1][3], b0, b1v);
                mma_f16h(hacc[0][p * 2 + 1], a[0][0], a[0][1], a[0][2], a[0][3], b2v, b3v);
                mma_f16h(hacc[1][p * 2 + 1], a[1][0], a[1][1], a[1][2], a[1][3], b2v, b3v);
            }
        }
    }
    __syncthreads();   // protect stage region

    // ---- epilogue: 2 passes of 128 cols (stride 130 floats)
    float* stage = (float*)(smem + SM_STG);
#pragma unroll 1
    for (int p = 0; p < 2; ++p) {
        if ((warp_n >> 1) == p) {
#pragma unroll
            for (int mt = 0; mt < 2; ++mt)
#pragma unroll
                for (int j = 0; j < 8; ++j) {
                    int r0 = warp_m * 32 + mt * 16 + gid;
                    int cw = (warp_n & 1) * 64 + j * 8 + tig * 2;
                    float* st = stage + r0 * 130 + cw;
                    float2 lo = __half22float2(*(__half2*)&hacc[mt][j][0]);
                    float2 hi = __half22float2(*(__half2*)&hacc[mt][j][1]);
                    st[0] = lo.x;
                    st[1] = lo.y;
                    st[130 * 8] = hi.x;
                    st[130 * 8 + 1] = hi.y;
                }
        }
        __syncthreads();
        {
            int colw = tid & 127;
            int grp = tid >> 7;
            int gcol = p * 128 + colw;
            float bias = b2[gcol];
            int prev = -1;
            float mx = 0.f;
#pragma unroll 4
            for (int r = grp * 32; r < grp * 32 + 32; ++r) {
                int d = sdst[r];
                float v = fmaxf(stage[r * 130 + colw] + bias, 0.f);
                if (d == prev) {
                    mx = fmaxf(mx, v);
                } else {
                    if (prev >= 0)
                        atomicMax((int*)&AGG[(size_t)prev * NOUT + gcol], __float_as_int(mx));
                    prev = d;
                    mx = v;
                }
            }
            atomicMax((int*)&AGG[(size_t)prev * NOUT + gcol], __float_as_int(mx));
        }
        __syncthreads();
    }
}

// ---------------- dense head ----------------
__global__ void k_head(const float* __restrict__ W3, const float* __restrict__ b3,
                       const float* __restrict__ W4, const float* __restrict__ b4,
                       float* __restrict__ out) {
    __shared__ float sh[128];
    __shared__ float red[2];
    int n = blockIdx.x;
    int t = threadIdx.x;   // 64 threads
    sh[t]      = g_H2[n * 128 + t];
    sh[t + 64] = g_H2[n * 128 + 64 + t];
    __syncthreads();
    float s = b3[t];
#pragma unroll 8
    for (int k = 0; k < 128; k++) s += sh[k] * W3[k * 64 + t];
    s = fmaxf(s, 0.f);
    float p = s * W4[t];
#pragma unroll
    for (int off = 16; off > 0; off >>= 1) p += __shfl_down_sync(0xffffffffu, p, off);
    if ((t & 31) == 0) red[t >> 5] = p;
    __syncthreads();
    if (t == 0) {
        float z = red[0] + red[1] + b4[0];
        out[n] = 1.f / (1.f + expf(-z));
    }
}

// ---------------- launch ----------------
extern "C" void kernel_launch(void* const* d_in, const int* in_sizes, int n_in,
                              void* d_out, int out_size) {
    const float* x   = (const float*)d_in[0];
    const int*   ei  = (const int*)d_in[1];
    const int*   src = ei;
    const int*   dst = ei + N_EDGES;
    const float* W1a = (const float*)d_in[2];
    const float* b1a = (const float*)d_in[3];
    const float* W2a = (const float*)d_in[4];
    const float* b2a = (const float*)d_in[5];
    const float* W1b = (const float*)d_in[6];
    const float* b1b = (const float*)d_in[7];
    const float* W2b = (const float*)d_in[8];
    const float* b2b = (const float*)d_in[9];
    const float* W3  = (const float*)d_in[10];
    const float* b3  = (const float*)d_in[11];
    const float* W4  = (const float*)d_in[12];
    const float* b4  = (const float*)d_in[13];
    float* out = (float*)d_out;

    void *pC1, *pD1, *pH1, *pC2, *pD2, *pH2, *pWT1, *pWT2, *pWTD1, *pWTD2;
    cudaGetSymbolAddress(&pC1, g_C1);
    cudaGetSymbolAddress(&pD1, g_D1);
    cudaGetSymbolAddress(&pH1, g_H1);
    cudaGetSymbolAddress(&pC2, g_C2);
    cudaGetSymbolAddress(&pD2, g_D2);
    cudaGetSymbolAddress(&pH2, g_H2);
    cudaGetSymbolAddress(&pWT1, g_WT1);
    cudaGetSymbolAddress(&pWT2, g_WT2);
    cudaGetSymbolAddress(&pWTD1, g_WTD1);
    cudaGetSymbolAddress(&pWTD2, g_WTD2);

    cudaFuncSetAttribute(k_edge_wide<512, 256>, cudaFuncAttributeMaxDynamicSharedMemorySize, WEDGE_SMEM);
    cudaFuncSetAttribute(k_edge_mma<256, 128>, cudaFuncAttributeMaxDynamicSharedMemorySize, EDGE_SMEM);
    cudaFuncSetAttribute(k_node_mma<128, 512>, cudaFuncAttributeMaxDynamicSharedMemorySize, NODE_SMEM);
    cudaFuncSetAttribute(k_node_mma<256, 256>, cudaFuncAttributeMaxDynamicSharedMemorySize, NODE_SMEM);

    // ---- fork: branch A (sort chain) on side stream, branch B (weights+node L1) on main
    cudaEventRecord(g_fork.e0, 0);
    cudaStreamWaitEvent(g_fork.s, g_fork.e0, 0);

    // branch A: zero + histogram + scan + scatter
    k_zero<<<512, 256, 0, g_fork.s>>>();
    k_hist<<<(N_EDGES + 255) / 256, 256, 0, g_fork.s>>>(dst);
    k_scan1<<<20, 512, 0, g_fork.s>>>();
    k_scatter<<<(N_EDGES + 255) / 256, 256, 0, g_fork.s>>>(src, dst);
    cudaEventRecord(g_fork.e1, g_fork.s);

    // branch B: weight prep + node GEMM layer 1
    k_prep<<<(294912 + 255) / 256, 256>>>(W2a, W2b, W1a, W1b);
    {
        dim3 g((N_NODES + 127) / 128, 1024 / 128);
        k_node_mma<128, 512><<<g, 256, NODE_SMEM>>>(x, (const __half*)pWTD1, b1a,
                                                    (__half*)pC1, (__half*)pD1);
    }

    // join: edge layer 1 needs both branches
    cudaStreamWaitEvent(0, g_fork.e1, 0);
    k_edge_wide<512, 256><<<N_EDGES / 128, 512, WEDGE_SMEM>>>(
        (const __half*)pC1, (const __half*)pD1,
        (const __half*)pWT1, b2a, (float*)pH1);

    // layer 2
    {
        dim3 g((N_NODES + 127) / 128, 512 / 128);
        k_node_mma<256, 256><<<g, 256, NODE_SMEM>>>((const float*)pH1, (const __half*)pWTD2, b1b,
                                                    (__half*)pC2, (__half*)pD2);
    }
    {
        dim3 g(N_EDGES / 128, 128 / 128);
        k_edge_mma<256, 128><<<g, 256, EDGE_SMEM>>>(
            (const __half*)pC2, (const __half*)pD2,
            (const __half*)pWT2, b2b, (float*)pH2);
    }

    // head
    k_head<<<N_NODES, 64>>>(W3, b3, W4, b4, out);
}

// round 17
// speedup vs baseline: 1.0330x; 1.0330x over previous
#include <cuda_runtime.h>
#include <cuda_fp16.h>
#include <stdint.h>
#include <math.h>

#define N_NODES 10000
#define N_EDGES 320000

// ---------------- scratch (static device allocations) ----------------
__device__ __half g_C1[N_NODES * 512];   // fp16: x@(W1top-W1bot) + b1
__device__ __half g_D1[N_NODES * 512];   // fp16: x@W1bot
__device__ float  g_H1[N_NODES * 256];
__device__ __half g_C2[N_NODES * 256];
__device__ __half g_D2[N_NODES * 256];
__device__ float  g_H2[N_NODES * 128];
__device__ int    g_hist[N_NODES + 1];
__device__ int    g_bsum[32];
__device__ int    g_cursor[N_NODES];
__device__ int    g_src_s[N_EDGES];
__device__ int    g_dst_s[N_EDGES];
__device__ __half g_WT1[256 * 512];
__device__ __half g_WT2[128 * 256];
__device__ __half g_WTD1[1024 * 128];
__device__ __half g_WTD2[512 * 256];

// ---------------- one-time stream/event creation (static init, pre-checkpoint) ----
struct GraphFork {
    cudaStream_t s;
    cudaEvent_t e0, e1;
    GraphFork() {
        cudaStreamCreateWithFlags(&s, cudaStreamNonBlocking);
        cudaEventCreateWithFlags(&e0, cudaEventDisableTiming);
        cudaEventCreateWithFlags(&e1, cudaEventDisableTiming);
    }
};
static GraphFork g_fork;

// ---------------- helpers ----------------
__device__ __forceinline__ uint32_t smem_u32(const void* p) {
    uint32_t a;
    asm("{ .reg .u64 t; cvta.to.shared.u64 t, %1; cvt.u32.u64 %0, t; }" : "=r"(a) : "l"(p));
    return a;
}
__device__ __forceinline__ void mma_f16(float* c,
    uint32_t a0, uint32_t a1, uint32_t a2, uint32_t a3,
    uint32_t b0, uint32_t b1) {
    asm volatile(
        "mma.sync.aligned.m16n8k16.row.col.f32.f16.f16.f32 "
        "{%0,%1,%2,%3}, {%4,%5,%6,%7}, {%8,%9}, {%0,%1,%2,%3};"
        : "+f"(c[0]), "+f"(c[1]), "+f"(c[2]), "+f"(c[3])
        : "r"(a0), "r"(a1), "r"(a2), "r"(a3), "r"(b0), "r"(b1));
}
__device__ __forceinline__ void ldsm4(uint32_t& r0, uint32_t& r1, uint32_t& r2, uint32_t& r3,
                                      uint32_t addr) {
    asm volatile("ldmatrix.sync.aligned.m8n8.x4.shared.b16 {%0,%1,%2,%3}, [%4];"
        : "=r"(r0), "=r"(r1), "=r"(r2), "=r"(r3) : "r"(addr));
}
__device__ __forceinline__ uint32_t haddrelu2(uint32_t a, uint32_t b) {
    __half2 av = *reinterpret_cast<__half2*>(&a);
    __half2 bv = *reinterpret_cast<__half2*>(&b);
    __half2 r = __hmax2(__hadd2(av, bv), __float2half2_rn(0.f));
    return *reinterpret_cast<uint32_t*>(&r);
}
__device__ __forceinline__ void cp16(uint32_t dst, const void* src) {
    asm volatile("cp.async.ca.shared.global [%0], [%1], 16;" :: "r"(dst), "l"(src) : "memory");
}
__device__ __forceinline__ void cp_commit() {
    asm volatile("cp.async.commit_group;" ::: "memory");
}
__device__ __forceinline__ void cp_wait_all() {
    asm volatile("cp.async.wait_group 0;" ::: "memory");
}

// lane offsets for LDSM fragment addressing (144B row stride tiles)
#define A_LANE_OFF(lid) ((uint32_t)(((lid) & 15) * 144 + ((lid) >> 4) * 16))
#define B_LANE_OFF(lid) ((uint32_t)(((((lid) >> 4) & 1) * 8 + ((lid) & 7)) * 144 + (((lid) >> 3) & 1) * 16))

// ---------------- init: hist/cursor/H1/H2 (branch A head) ----------------
__global__ void k_zero() {
    int stride = gridDim.x * blockDim.x;
    int i0 = blockIdx.x * blockDim.x + threadIdx.x;
    float4 z4 = make_float4(0.f, 0.f, 0.f, 0.f);
    for (int j = i0; j < N_NODES * 64; j += stride) ((float4*)g_H1)[j] = z4;
    for (int j = i0; j < N_NODES * 32; j += stride) ((float4*)g_H2)[j] = z4;
    for (int j = i0; j <= N_NODES;     j += stride) g_hist[j] = 0;
    for (int j = i0; j < N_NODES;      j += stride) g_cursor[j] = 0;
}

// ---------------- histogram (branch A) ----------------
__global__ void k_hist(const int* __restrict__ dst) {
    int e = blockIdx.x * blockDim.x + threadIdx.x;
    if (e < N_EDGES) atomicAdd(&g_hist[dst[e] + 1], 1);
}

// ---------------- weight preps (branch B) ----------------
__global__ void k_prep(const float* __restrict__ W2a, const float* __restrict__ W2b,
                       const float* __restrict__ W1a, const float* __restrict__ W1b) {
    int i = blockIdx.x * blockDim.x + threadIdx.x;
    if (i < 131072) {
        int n = i >> 9, k = i & 511;       // WT1: [256,512] from W2a [512,256]
        g_WT1[i] = __float2half_rn(W2a[k * 256 + n]);
    } else if (i < 163840) {
        int i2 = i - 131072;               // WT2: [128,256] from W2b [256,128]
        int n = i2 >> 8, k = i2 & 255;
        g_WT2[i2] = __float2half_rn(W2b[k * 128 + n]);
    } else if (i < 229376) {
        int i2 = i - 163840;               // WTD1: dual [1024,128] from W1a [256,512]
        int n = i2 >> 7, k = i2 & 127;
        float top = W1a[k * 512 + n];
        float bot = W1a[(128 + k) * 512 + n];
        g_WTD1[n * 128 + k] = __float2half_rn(top - bot);
        g_WTD1[(512 + n) * 128 + k] = __float2half_rn(bot);
    } else if (i < 294912) {
        int i2 = i - 229376;               // WTD2: dual [512,256] from W1b [512,256]
        int n = i2 >> 8, k = i2 & 255;
        float top = W1b[k * 256 + n];
        float bot = W1b[(256 + k) * 256 + n];
        g_WTD2[n * 256 + k] = __float2half_rn(top - bot);
        g_WTD2[(256 + n) * 256 + k] = __float2half_rn(bot);
    }
}

// ---------------- counting-sort scan + scatter (branch A) ----------------
__global__ void k_scan1() {
    __shared__ int s[512];
    int b = blockIdx.x, t = threadIdx.x;
    int i = b * 512 + t;
    int v = (i < N_NODES + 1) ? g_hist[i] : 0;
    s[t] = v;
    __syncthreads();
    for (int off = 1; off < 512; off <<= 1) {
        int u = (t >= off) ? s[t - off] : 0;
        __syncthreads();
        s[t] += u;
        __syncthreads();
    }
    if (i < N_NODES + 1) g_hist[i] = s[t];
    if (t == 511) g_bsum[b] = s[511];
}
__global__ void k_scatter(const int* __restrict__ src, const int* __restrict__ dst) {
    __shared__ int lut[20];
    int t = threadIdx.x;
    if (t < 32) {
        int v = (t < 20) ? g_bsum[t] : 0;
        int inc = v;
#pragma unroll
        for (int off = 1; off < 32; off <<= 1) {
            int u = __shfl_up_sync(0xffffffffu, inc, off);
            if (t >= off) inc += u;
        }
        if (t < 20) lut[t] = inc - v;   // exclusive prefix
    }
    __syncthreads();
    int e = blockIdx.x * blockDim.x + t;
    if (e < N_EDGES) {
        int d = dst[e];
        int pos = g_hist[d] + lut[d >> 9] + atomicAdd(&g_cursor[d], 1);
        g_src_s[pos] = src[e];
        g_dst_s[pos] = d;
    }
}

// ---------------- node fp16 MMA GEMM: [C | D] = fp16(X) @ WTdual^T ----------------
#define NODE_SMEM 36864

template <int K, int NOUT>
__global__ void __launch_bounds__(256, 2) k_node_mma(
    const float* __restrict__ X, const __half* __restrict__ WT,
    const float* __restrict__ b1, __half* __restrict__ C, __half* __restrict__ D)
{
    extern __shared__ char smem[];
    const uint32_t sb = smem_u32(smem);
    const int tid = threadIdx.x;
    const int wid = tid >> 5, lid = tid & 31;
    const int warp_m = wid & 3, warp_n = wid >> 2;
    const int gid = lid >> 2, tig = lid & 3;

    const int m0 = blockIdx.x * 128;
    const int n0 = blockIdx.y * 128;

    const int fm = tid >> 1;
    const int fk = (tid & 1) * 32;
    const int gm = m0 + fm;
    const bool valid = gm < N_NODES;
    const float* rowX = X + (size_t)(valid ? gm : 0) * K + fk;
    const __half* rowW = WT + (size_t)(n0 + fm) * K + fk;

    const uint32_t aA = sb + (uint32_t)(warp_m * 32) * 144 + A_LANE_OFF(lid);
    const uint32_t aB = sb + 18432 + (uint32_t)(warp_n * 64) * 144 + B_LANE_OFF(lid);

    float acc[2][8][4];
#pragma unroll
    for (int a = 0; a < 2; ++a)
#pragma unroll
        for (int b = 0; b < 8; ++b)
#pragma unroll
            for (int c = 0; c < 4; ++c) acc[a][b][c] = 0.f;

    constexpr int NCH = K / 64;
#pragma unroll 1
    for (int ch = 0; ch < NCH; ++ch) {
        {
            const uint4* wp = (const uint4*)(rowW + ch * 64);
            uint4 w0 = wp[0], w1 = wp[1], w2 = wp[2], w3 = wp[3];
            char* pb = smem + 18432 + fm * 144 + fk * 2;
            *(uint4*)pb        = w0;
            *(uint4*)(pb + 16) = w1;
            *(uint4*)(pb + 32) = w2;
            *(uint4*)(pb + 48) = w3;
        }
        {
            char* pa = smem + fm * 144 + fk * 2;
#pragma unroll
            for (int q = 0; q < 4; ++q) {
                float4 x0 = make_float4(0.f, 0.f, 0.f, 0.f);
                float4 x1 = make_float4(0.f, 0.f, 0.f, 0.f);
                if (valid) {
                    x0 = *(const float4*)(rowX + ch * 64 + q * 8);
                    x1 = *(const float4*)(rowX + ch * 64 + q * 8 + 4);
                }
                __half2 h0 = __floats2half2_rn(x0.x, x0.y);
                __half2 h1 = __floats2half2_rn(x0.z, x0.w);
                __half2 h2 = __floats2half2_rn(x1.x, x1.y);
                __half2 h3 = __floats2half2_rn(x1.z, x1.w);
                *(uint4*)(pa + q * 16) = make_uint4(
                    *(uint32_t*)&h0, *(uint32_t*)&h1, *(uint32_t*)&h2, *(uint32_t*)&h3);
            }
        }
        __syncthreads();
#pragma unroll
        for (int ks = 0; ks < 4; ++ks) {
            uint32_t a[2][4];
            ldsm4(a[0][0], a[0][1], a[0][2], a[0][3], aA + ks * 32);
            ldsm4(a[1][0], a[1][1], a[1][2], a[1][3], aA + 16 * 144 + ks * 32);
#pragma unroll
            for (int p = 0; p < 4; ++p) {
                uint32_t b0, b1v, b2v, b3v;
                ldsm4(b0, b1v, b2v, b3v, aB + (uint32_t)(p * 16) * 144 + ks * 32);
                mma_f16(acc[0][p * 2],     a[0][0], a[0][1], a[0][2], a[0][3], b0, b1v);
                mma_f16(acc[1][p * 2],     a[1][0], a[1][1], a[1][2], a[1][3], b0, b1v);
                mma_f16(acc[0][p * 2 + 1], a[0][0], a[0][1], a[0][2], a[0][3], b2v, b3v);
                mma_f16(acc[1][p * 2 + 1], a[1][0], a[1][1], a[1][2], a[1][3], b2v, b3v);
            }
        }
        __syncthreads();
    }

    const bool isC = (n0 < NOUT);
    __half* OUT = isC ? C : D;
    const int cb = isC ? n0 : n0 - NOUT;
#pragma unroll
    for (int mt = 0; mt < 2; ++mt)
#pragma unroll
        for (int j = 0; j < 8; ++j) {
            int r = m0 + warp_m * 32 + mt * 16 + gid;
            int c = cb + warp_n * 64 + j * 8 + tig * 2;
            float bb0 = 0.f, bb1 = 0.f;
            if (isC) { bb0 = __ldg(b1 + c); bb1 = __ldg(b1 + c + 1); }
            if (r < N_NODES) {
                __half2 h = __floats2half2_rn(acc[mt][j][0] + bb0, acc[mt][j][1] + bb1);
                *(__half2*)&OUT[(size_t)r * NOUT + c] = h;
            }
            if (r + 8 < N_NODES) {
                __half2 h = __floats2half2_rn(acc[mt][j][2] + bb0, acc[mt][j][3] + bb1);
                *(__half2*)&OUT[(size_t)(r + 8) * NOUT + c] = h;
            }
        }
}

// ---------------- layer-2 edge GEMM: 256 thr, tile 128x128, A+B double-buffered ----------
#define SM_SDST 0
#define SM_SSRC 512
#define SM_A0   1024
#define SM_A1   19456
#define SM_B0   37888
#define SM_B1   56320
#define SM_STG  1024
#define EDGE_SMEM 74752

template <int KW, int NOUT>
__global__ void __launch_bounds__(256, 2) k_edge_mma(
    const __half* __restrict__ C, const __half* __restrict__ D,
    const __half* __restrict__ WT, const float* __restrict__ b2, float* __restrict__ AGG)
{
    extern __shared__ char smem[];
    const uint32_t sb = smem_u32(smem);
    const int tid = threadIdx.x;
    const int wid = tid >> 5, lid = tid & 31;
    const int warp_m = wid & 3, warp_n = wid >> 2;
    const int gid = lid >> 2, tig = lid & 3;

    int* sdst = (int*)(smem + SM_SDST);
    int* ssrc = (int*)(smem + SM_SSRC);

    const int e0 = blockIdx.x * 128;
    const int n0 = blockIdx.y * 128;
    if (tid < 128) {
        sdst[tid] = g_dst_s[e0 + tid];
        ssrc[tid] = g_src_s[e0 + tid];
    }
    __syncthreads();

    const int fm = tid >> 1;
    const int fk = (tid & 1) * 32;
    const __half* rowC = C + (size_t)sdst[fm] * KW + fk;
    const __half* rowD = D + (size_t)ssrc[fm] * KW + fk;
    const __half* rowW = WT + (size_t)(n0 + fm) * KW + fk;
    const uint32_t bdst0 = sb + SM_B0 + fm * 144 + fk * 2;
    const uint32_t bdst1 = sb + SM_B1 + fm * 144 + fk * 2;

    const uint32_t aOffA = (uint32_t)(warp_m * 32) * 144 + A_LANE_OFF(lid);
    const uint32_t aOffB = (uint32_t)(warp_n * 64) * 144 + B_LANE_OFF(lid);

    float acc[2][8][4];
#pragma unroll
    for (int a = 0; a < 2; ++a)
#pragma unroll
        for (int b = 0; b < 8; ++b)
#pragma unroll
            for (int c = 0; c < 4; ++c) acc[a][b][c] = 0.f;

    constexpr int NCH = KW / 64;
    uint4 pc[4], pd[4];
    {
        const uint4* cp = (const uint4*)rowC;
        const uint4* dp = (const uint4*)rowD;
#pragma unroll
        for (int q = 0; q < 4; ++q) { pc[q] = cp[q]; pd[q] = dp[q]; }
        cp16(bdst0,      rowW);
        cp16(bdst0 + 16, rowW + 8);
        cp16(bdst0 + 32, rowW + 16);
        cp16(bdst0 + 48, rowW + 24);
        cp_commit();
    }

#pragma unroll 1
    for (int ch = 0; ch < NCH; ++ch) {
        uint4 ao[4];
#pragma unroll
        for (int q = 0; q < 4; ++q) {
            ao[q].x = haddrelu2(pc[q].x, pd[q].x);
            ao[q].y = haddrelu2(pc[q].y, pd[q].y);
            ao[q].z = haddrelu2(pc[q].z, pd[q].z);
            ao[q].w = haddrelu2(pc[q].w, pd[q].w);
        }
        if (ch + 1 < NCH) {   // early gather issue
            const uint4* cp = (const uint4*)(rowC + (ch + 1) * 64);
            const uint4* dp = (const uint4*)(rowD + (ch + 1) * 64);
#pragma unroll
            for (int q = 0; q < 4; ++q) { pc[q] = cp[q]; pd[q] = dp[q]; }
        }
        {
            char* pa = smem + ((ch & 1) ? SM_A1 : SM_A0) + fm * 144 + fk * 2;
            *(uint4*)pa        = ao[0];
            *(uint4*)(pa + 16) = ao[1];
            *(uint4*)(pa + 32) = ao[2];
            *(uint4*)(pa + 48) = ao[3];
        }
        cp_wait_all();
        __syncthreads();
        if (ch + 1 < NCH) {
            const __half* ws = rowW + (ch + 1) * 64;
            uint32_t bd = ((ch + 1) & 1) ? bdst1 : bdst0;
            cp16(bd,      ws);
            cp16(bd + 16, ws + 8);
            cp16(bd + 32, ws + 16);
            cp16(bd + 48, ws + 24);
            cp_commit();
        }
        const uint32_t abase = sb + ((ch & 1) ? SM_A1 : SM_A0) + aOffA;
        const uint32_t bbase = sb + ((ch & 1) ? SM_B1 : SM_B0) + aOffB;
#pragma unroll
        for (int ks = 0; ks < 4; ++ks) {
            uint32_t a[2][4];
            ldsm4(a[0][0], a[0][1], a[0][2], a[0][3], abase + ks * 32);
            ldsm4(a[1][0], a[1][1], a[1][2], a[1][3], abase + 16 * 144 + ks * 32);
#pragma unroll
            for (int p = 0; p < 4; ++p) {
                uint32_t b0, b1v, b2v, b3v;
                ldsm4(b0, b1v, b2v, b3v, bbase + (uint32_t)(p * 16) * 144 + ks * 32);
                mma_f16(acc[0][p * 2],     a[0][0], a[0][1], a[0][2], a[0][3], b0, b1v);
                mma_f16(acc[1][p * 2],     a[1][0], a[1][1], a[1][2], a[1][3], b0, b1v);
                mma_f16(acc[0][p * 2 + 1], a[0][0], a[0][1], a[0][2], a[0][3], b2v, b3v);
                mma_f16(acc[1][p * 2 + 1], a[1][0], a[1][1], a[1][2], a[1][3], b2v, b3v);
            }
        }
    }
    __syncthreads();   // protect stage region (overlaps A/B buffers)

    // ---- epilogue: single pass, all 128 cols staged (stride 130 floats)
    float* stage = (float*)(smem + SM_STG);
#pragma unroll
    for (int mt = 0; mt < 2; ++mt)
#pragma unroll
        for (int j = 0; j < 8; ++j) {
            int r0 = warp_m * 32 + mt * 16 + gid;
            int cw = warp_n * 64 + j * 8 + tig * 2;
            float* st = stage + r0 * 130 + cw;
            st[0] = acc[mt][j][0];
            st[1] = acc[mt][j][1];
            st[130 * 8] = acc[mt][j][2];
            st[130 * 8 + 1] = acc[mt][j][3];
        }
    __syncthreads();
    {
        int colw = tid & 127;
        int grp = tid >> 7;
        int gcol = n0 + colw;
        float bias = b2[gcol];
        int prev = -1;
        float mx = 0.f;
#pragma unroll 4
        for (int r = grp * 64; r < grp * 64 + 64; ++r) {
            int d = sdst[r];
            float v = fmaxf(stage[r * 130 + colw] + bias, 0.f);
            if (d == prev) {
                mx = fmaxf(mx, v);
            } else {
                if (prev >= 0)
                    atomicMax((int*)&AGG[(size_t)prev * NOUT + gcol], __float_as_int(mx));
                prev = d;
                mx = v;
            }
        }
        atomicMax((int*)&AGG[(size_t)prev * NOUT + gcol], __float_as_int(mx));
    }
}

// ---------------- layer-1 edge GEMM: 512 thr, tile 128x256, A+B double-buffered -------
#define WSM_A0 1024
#define WSM_A1 19456
#define WSM_B0 37888
#define WSM_B1 74752
#define WEDGE_SMEM 111616

template <int KW, int NOUT>
__global__ void __launch_bounds__(512, 1) k_edge_wide(
    const __half* __restrict__ C, const __half* __restrict__ D,
    const __half* __restrict__ WT, const float* __restrict__ b2, float* __restrict__ AGG)
{
    extern __shared__ char smem[];
    const uint32_t sb = smem_u32(smem);
    const int tid = threadIdx.x;
    const int wid = tid >> 5, lid = tid & 31;
    const int warp_m = wid & 3, warp_n = wid >> 2;   // 4 x 4
    const int gid = lid >> 2, tig = lid & 3;

    int* sdst = (int*)(smem + SM_SDST);
    int* ssrc = (int*)(smem + SM_SSRC);

    const int e0 = blockIdx.x * 128;
    if (tid < 128) {
        sdst[tid] = g_dst_s[e0 + tid];
        ssrc[tid] = g_src_s[e0 + tid];
    }
    __syncthreads();

    const int fm = tid >> 2;
    const int fq = (tid & 3) * 16;
    const int wm = tid >> 1;
    const int wq = (tid & 1) * 32;
    const __half* rowC = C + (size_t)sdst[fm] * KW + fq;
    const __half* rowD = D + (size_t)ssrc[fm] * KW + fq;
    const __half* rowW = WT + (size_t)wm * KW + wq;
    const uint32_t bdst0 = sb + WSM_B0 + wm * 144 + wq * 2;
    const uint32_t bdst1 = sb + WSM_B1 + wm * 144 + wq * 2;

    const uint32_t aOffA = (uint32_t)(warp_m * 32) * 144 + A_LANE_OFF(lid);
    const uint32_t aOffB = (uint32_t)(warp_n * 64) * 144 + B_LANE_OFF(lid);

    float acc[2][8][4];
#pragma unroll
    for (int a = 0; a < 2; ++a)
#pragma unroll
        for (int b = 0; b < 8; ++b)
#pragma unroll
            for (int c = 0; c < 4; ++c) acc[a][b][c] = 0.f;

    constexpr int NCH = KW / 64;
    uint4 pc[2], pd[2];
    {
        const uint4* cp = (const uint4*)rowC;
        const uint4* dp = (const uint4*)rowD;
        pc[0] = cp[0]; pc[1] = cp[1];
        pd[0] = dp[0]; pd[1] = dp[1];
        cp16(bdst0,      rowW);
        cp16(bdst0 + 16, rowW + 8);
        cp16(bdst0 + 32, rowW + 16);
        cp16(bdst0 + 48, rowW + 24);
        cp_commit();
    }

#pragma unroll 1
    for (int ch = 0; ch < NCH; ++ch) {
        uint4 ao[2];
#pragma unroll
        for (int q = 0; q < 2; ++q) {
            ao[q].x = haddrelu2(pc[q].x, pd[q].x);
            ao[q].y = haddrelu2(pc[q].y, pd[q].y);
            ao[q].z = haddrelu2(pc[q].z, pd[q].z);
            ao[q].w = haddrelu2(pc[q].w, pd[q].w);
        }
        if (ch + 1 < NCH) {   // early gather issue
            const uint4* cp = (const uint4*)(rowC + (ch + 1) * 64);
            const uint4* dp = (const uint4*)(rowD + (ch + 1) * 64);
            pc[0] = cp[0]; pc[1] = cp[1];
            pd[0] = dp[0]; pd[1] = dp[1];
        }
        {
            char* pa = smem + ((ch & 1) ? WSM_A1 : WSM_A0) + fm * 144 + fq * 2;
            *(uint4*)pa        = ao[0];
            *(uint4*)(pa + 16) = ao[1];
        }
        cp_wait_all();
        __syncthreads();
        if (ch + 1 < NCH) {
            const __half* ws = rowW + (ch + 1) * 64;
            uint32_t bd = ((ch + 1) & 1) ? bdst1 : bdst0;
            cp16(bd,      ws);
            cp16(bd + 16, ws + 8);
            cp16(bd + 32, ws + 16);
            cp16(bd + 48, ws + 24);
            cp_commit();
        }
        const uint32_t abase = sb + ((ch & 1) ? WSM_A1 : WSM_A0) + aOffA;
        const uint32_t bbase = sb + ((ch & 1) ? WSM_B1 : WSM_B0) + aOffB;
#pragma unroll
        for (int ks = 0; ks < 4; ++ks) {
            uint32_t a[2][4];
            ldsm4(a[0][0], a[0][1], a[0][2], a[0][3], abase + ks * 32);
            ldsm4(a[1][0], a[1][1], a[1][2], a[1][3], abase + 16 * 144 + ks * 32);
#pragma unroll
            for (int p = 0; p < 4; ++p) {
                uint32_t b0, b1v, b2v, b3v;
                ldsm4(b0, b1v, b2v, b3v, bbase + (uint32_t)(p * 16) * 144 + ks * 32);
                mma_f16(acc[0][p * 2],     a[0][0], a[0][1], a[0][2], a[0][3], b0, b1v);
                mma_f16(acc[1][p * 2],     a[1][0], a[1][1], a[1][2], a[1][3], b0, b1v);
                mma_f16(acc[0][p * 2 + 1], a[0][0], a[0][1], a[0][2], a[0][3], b2v, b3v);
                mma_f16(acc[1][p * 2 + 1], a[1][0], a[1][1], a[1][2], a[1][3], b2v, b3v);
            }
        }
    }
    __syncthreads();   // protect stage region

    // ---- epilogue: 2 passes of 128 cols (stride 130 floats)
    float* stage = (float*)(smem + SM_STG);
#pragma unroll 1
    for (int p = 0; p < 2; ++p) {
        if ((warp_n >> 1) == p) {
#pragma unroll
            for (int mt = 0; mt < 2; ++mt)
#pragma unroll
                for (int j = 0; j < 8; ++j) {
                    int r0 = warp_m * 32 + mt * 16 + gid;
                    int cw = (warp_n & 1) * 64 + j * 8 + tig * 2;
                    float* st = stage + r0 * 130 + cw;
                    st[0] = acc[mt][j][0];
                    st[1] = acc[mt][j][1];
                    st[130 * 8] = acc[mt][j][2];
                    st[130 * 8 + 1] = acc[mt][j][3];
                }
        }
        __syncthreads();
        {
            int colw = tid & 127;
            int grp = tid >> 7;
            int gcol = p * 128 + colw;
            float bias = b2[gcol];
            int prev = -1;
            float mx = 0.f;
#pragma unroll 4
            for (int r = grp * 32; r < grp * 32 + 32; ++r) {
                int d = sdst[r];
                float v = fmaxf(stage[r * 130 + colw] + bias, 0.f);
                if (d == prev) {
                    mx = fmaxf(mx, v);
                } else {
                    if (prev >= 0)
                        atomicMax((int*)&AGG[(size_t)prev * NOUT + gcol], __float_as_int(mx));
                    prev = d;
                    mx = v;
                }
            }
            atomicMax((int*)&AGG[(size_t)prev * NOUT + gcol], __float_as_int(mx));
        }
        __syncthreads();
    }
}

// ---------------- dense head ----------------
__global__ void k_head(const float* __restrict__ W3, const float* __restrict__ b3,
                       const float* __restrict__ W4, const float* __restrict__ b4,
                       float* __restrict__ out) {
    __shared__ float sh[128];
    __shared__ float red[2];
    int n = blockIdx.x;
    int t = threadIdx.x;   // 64 threads
    sh[t]      = g_H2[n * 128 + t];
    sh[t + 64] = g_H2[n * 128 + 64 + t];
    __syncthreads();
    float s = b3[t];
#pragma unroll 8
    for (int k = 0; k < 128; k++) s += sh[k] * W3[k * 64 + t];
    s = fmaxf(s, 0.f);
    float p = s * W4[t];
#pragma unroll
    for (int off = 16; off > 0; off >>= 1) p += __shfl_down_sync(0xffffffffu, p, off);
    if ((t & 31) == 0) red[t >> 5] = p;
    __syncthreads();
    if (t == 0) {
        float z = red[0] + red[1] + b4[0];
        out[n] = 1.f / (1.f + expf(-z));
    }
}

// ---------------- launch ----------------
extern "C" void kernel_launch(void* const* d_in, const int* in_sizes, int n_in,
                              void* d_out, int out_size) {
    const float* x   = (const float*)d_in[0];
    const int*   ei  = (const int*)d_in[1];
    const int*   src = ei;
    const int*   dst = ei + N_EDGES;
    const float* W1a = (const float*)d_in[2];
    const float* b1a = (const float*)d_in[3];
    const float* W2a = (const float*)d_in[4];
    const float* b2a = (const float*)d_in[5];
    const float* W1b = (const float*)d_in[6];
    const float* b1b = (const float*)d_in[7];
    const float* W2b = (const float*)d_in[8];
    const float* b2b = (const float*)d_in[9];
    const float* W3  = (const float*)d_in[10];
    const float* b3  = (const float*)d_in[11];
    const float* W4  = (const float*)d_in[12];
    const float* b4  = (const float*)d_in[13];
    float* out = (float*)d_out;

    void *pC1, *pD1, *pH1, *pC2, *pD2, *pH2, *pWT1, *pWT2, *pWTD1, *pWTD2;
    cudaGetSymbolAddress(&pC1, g_C1);
    cudaGetSymbolAddress(&pD1, g_D1);
    cudaGetSymbolAddress(&pH1, g_H1);
    cudaGetSymbolAddress(&pC2, g_C2);
    cudaGetSymbolAddress(&pD2, g_D2);
    cudaGetSymbolAddress(&pH2, g_H2);
    cudaGetSymbolAddress(&pWT1, g_WT1);
    cudaGetSymbolAddress(&pWT2, g_WT2);
    cudaGetSymbolAddress(&pWTD1, g_WTD1);
    cudaGetSymbolAddress(&pWTD2, g_WTD2);

    cudaFuncSetAttribute(k_edge_wide<512, 256>, cudaFuncAttributeMaxDynamicSharedMemorySize, WEDGE_SMEM);
    cudaFuncSetAttribute(k_edge_mma<256, 128>, cudaFuncAttributeMaxDynamicSharedMemorySize, EDGE_SMEM);
    cudaFuncSetAttribute(k_node_mma<128, 512>, cudaFuncAttributeMaxDynamicSharedMemorySize, NODE_SMEM);
    cudaFuncSetAttribute(k_node_mma<256, 256>, cudaFuncAttributeMaxDynamicSharedMemorySize, NODE_SMEM);

    // ---- fork: branch A (sort chain) on side stream, branch B (weights+node L1) on main
    cudaEventRecord(g_fork.e0, 0);
    cudaStreamWaitEvent(g_fork.s, g_fork.e0, 0);

    // branch A: zero + histogram + scan + scatter
    k_zero<<<512, 256, 0, g_fork.s>>>();
    k_hist<<<(N_EDGES + 255) / 256, 256, 0, g_fork.s>>>(dst);
    k_scan1<<<20, 512, 0, g_fork.s>>>();
    k_scatter<<<(N_EDGES + 255) / 256, 256, 0, g_fork.s>>>(src, dst);
    cudaEventRecord(g_fork.e1, g_fork.s);

    // branch B: weight prep + node GEMM layer 1
    k_prep<<<(294912 + 255) / 256, 256>>>(W2a, W2b, W1a, W1b);
    {
        dim3 g((N_NODES + 127) / 128, 1024 / 128);
        k_node_mma<128, 512><<<g, 256, NODE_SMEM>>>(x, (const __half*)pWTD1, b1a,
                                                    (__half*)pC1, (__half*)pD1);
    }

    // join: edge layer 1 needs both branches
    cudaStreamWaitEvent(0, g_fork.e1, 0);
    k_edge_wide<512, 256><<<N_EDGES / 128, 512, WEDGE_SMEM>>>(
        (const __half*)pC1, (const __half*)pD1,
        (const __half*)pWT1, b2a, (float*)pH1);

    // layer 2
    {
        dim3 g((N_NODES + 127) / 128, 512 / 128);
        k_node_mma<256, 256><<<g, 256, NODE_SMEM>>>((const float*)pH1, (const __half*)pWTD2, b1b,
                                                    (__half*)pC2, (__half*)pD2);
    }
    {
        dim3 g(N_EDGES / 128, 128 / 128);
        k_edge_mma<256, 128><<<g, 256, EDGE_SMEM>>>(
            (const __half*)pC2, (const __half*)pD2,
            (const __half*)pWT2, b2b, (float*)pH2);
    }

    // head
    k_head<<<N_NODES, 64>>>(W3, b3, W4, b4, out);
}